// round 16
// baseline (speedup 1.0000x reference)
#include <cuda_runtime.h>
#include <math.h>
#include <stdint.h>

#define Hd     1024
#define G4     4096
#define Vocab  32000
#define NBLK   148
#define NTHR   1024
#define NWARP  32
#define TOTW   (NBLK * NWARP)   // 4736
#define LEFT   (Vocab - 6 * TOTW)   // 3584 leftover rows
#define MAXSTEPS 192

// ---------------- persistent device scratch (no allocations allowed) --------
__device__ float g_gate0[G4];     // layer-0 gate pre-act (W_hh0·h0 + biases)
__device__ float g_gate1[G4];     // layer-1 gate pre-act (full)
__device__ float g_hinit[Hd];
__device__ unsigned long long g_argmax[MAXSTEPS];
__device__ float g_partial[MAXSTEPS][NBLK];
__device__ unsigned long long g_bar;

__global__ void dec_init()
{
    if (threadIdx.x == 0) g_bar = 0ULL;
    for (int t = threadIdx.x; t < MAXSTEPS; t += blockDim.x) g_argmax[t] = 0ULL;
}

__device__ __forceinline__ float sigmoidf_(float x)
{
    return 1.f / (1.f + expf(-x));
}

__device__ __forceinline__ float warp_reduce_add(float v)
{
#pragma unroll
    for (int o = 16; o; o >>= 1) v += __shfl_xor_sync(0xffffffffu, v, o);
    return v;
}

// ---- 256-bit L2 eviction-policy loads (sm_103a: evict_* needs v8.b32) ------
struct F8 { float v[8]; };

__device__ __forceinline__ F8 ld256_evl(const float* p)   // keep in L2
{
    unsigned r0, r1, r2, r3, r4, r5, r6, r7;
    asm("ld.global.nc.L2::evict_last.v8.b32 {%0,%1,%2,%3,%4,%5,%6,%7}, [%8];"
        : "=r"(r0), "=r"(r1), "=r"(r2), "=r"(r3),
          "=r"(r4), "=r"(r5), "=r"(r6), "=r"(r7)
        : "l"(p));
    F8 f;
    f.v[0] = __uint_as_float(r0); f.v[1] = __uint_as_float(r1);
    f.v[2] = __uint_as_float(r2); f.v[3] = __uint_as_float(r3);
    f.v[4] = __uint_as_float(r4); f.v[5] = __uint_as_float(r5);
    f.v[6] = __uint_as_float(r6); f.v[7] = __uint_as_float(r7);
    return f;
}

__device__ __forceinline__ F8 ld256_evf(const float* p)   // stream through L2
{
    unsigned r0, r1, r2, r3, r4, r5, r6, r7;
    asm("ld.global.nc.L2::evict_first.v8.b32 {%0,%1,%2,%3,%4,%5,%6,%7}, [%8];"
        : "=r"(r0), "=r"(r1), "=r"(r2), "=r"(r3),
          "=r"(r4), "=r"(r5), "=r"(r6), "=r"(r7)
        : "l"(p));
    F8 f;
    f.v[0] = __uint_as_float(r0); f.v[1] = __uint_as_float(r1);
    f.v[2] = __uint_as_float(r2); f.v[3] = __uint_as_float(r3);
    f.v[4] = __uint_as_float(r4); f.v[5] = __uint_as_float(r5);
    f.v[6] = __uint_as_float(r6); f.v[7] = __uint_as_float(r7);
    return f;
}

__device__ __forceinline__ float f8_dot_sh(const F8& a, const float4* h4,
                                           int base)
{
    float4 u0 = h4[base];
    float4 u1 = h4[base + 1];
    return a.v[0] * u0.x + a.v[1] * u0.y + a.v[2] * u0.z + a.v[3] * u0.w
         + a.v[4] * u1.x + a.v[5] * u1.y + a.v[6] * u1.z + a.v[7] * u1.w;
}

// plain warp dot (init only)
__device__ __forceinline__ float warp_dot(const float* __restrict__ w,
                                          const float* __restrict__ sh,
                                          int lane)
{
    const float4* w4 = reinterpret_cast<const float4*>(w);
    const float4* h4 = reinterpret_cast<const float4*>(sh);
    float a0 = 0.f;
#pragma unroll
    for (int it = 0; it < 8; ++it) {
        float4 x = w4[it * 32 + lane];
        float4 u = h4[it * 32 + lane];
        a0 += x.x * u.x + x.y * u.y + x.z * u.z + x.w * u.w;
    }
    return warp_reduce_add(a0);
}

// L2-resident (evict_last) warp dot — LSTM weights
__device__ __forceinline__ float warp_dot_evl(const float* __restrict__ w,
                                              const float* __restrict__ sh,
                                              int lane)
{
    const float4* h4 = reinterpret_cast<const float4*>(sh);
    float a0 = 0.f;
#pragma unroll
    for (int it = 0; it < 4; ++it) {
        F8 x = ld256_evl(w + it * 256 + lane * 8);
        a0 += f8_dot_sh(x, h4, it * 64 + lane * 2);
    }
    return warp_reduce_add(a0);
}

// streaming single-row dot (W_out leftover row)
__device__ __forceinline__ float warp_dot_evf(const float* __restrict__ w,
                                              const float* __restrict__ sh,
                                              int lane)
{
    const float4* h4 = reinterpret_cast<const float4*>(sh);
    float a0 = 0.f;
#pragma unroll
    for (int it = 0; it < 4; ++it) {
        F8 x = ld256_evf(w + it * 256 + lane * 8);
        a0 += f8_dot_sh(x, h4, it * 64 + lane * 2);
    }
    return warp_reduce_add(a0);
}

// two rows against two different vectors, evict_last (recurrent dots)
__device__ __forceinline__ void warp_dot_pair2_evl(const float* __restrict__ w1,
                                                   const float* __restrict__ s1,
                                                   const float* __restrict__ w2,
                                                   const float* __restrict__ s2,
                                                   int lane, float& o1, float& o2)
{
    const float4* h4 = reinterpret_cast<const float4*>(s1);
    const float4* g4 = reinterpret_cast<const float4*>(s2);
    float p = 0.f, q = 0.f;
#pragma unroll
    for (int it = 0; it < 4; ++it) {
        F8 a = ld256_evl(w1 + it * 256 + lane * 8);
        F8 b = ld256_evl(w2 + it * 256 + lane * 8);
        p += f8_dot_sh(a, h4, it * 64 + lane * 2);
        q += f8_dot_sh(b, g4, it * 64 + lane * 2);
    }
#pragma unroll
    for (int o = 16; o; o >>= 1) {
        p += __shfl_xor_sync(0xffffffffu, p, o);
        q += __shfl_xor_sync(0xffffffffu, q, o);
    }
    o1 = p; o2 = q;
}

// two independent W_out rows vs same vector; policy chosen per call (warp-uniform)
__device__ __forceinline__ void warp_dot_pair_pol(const float* __restrict__ w1,
                                                  const float* __restrict__ w2,
                                                  const float* __restrict__ sh,
                                                  int lane, bool cached,
                                                  float& o1, float& o2)
{
    const float4* h4 = reinterpret_cast<const float4*>(sh);
    float p = 0.f, q = 0.f;
    if (cached) {
#pragma unroll
        for (int it = 0; it < 4; ++it) {
            F8 a = ld256_evl(w1 + it * 256 + lane * 8);
            F8 b = ld256_evl(w2 + it * 256 + lane * 8);
            p += f8_dot_sh(a, h4, it * 64 + lane * 2);
            q += f8_dot_sh(b, h4, it * 64 + lane * 2);
        }
    } else {
#pragma unroll
        for (int it = 0; it < 4; ++it) {
            F8 a = ld256_evf(w1 + it * 256 + lane * 8);
            F8 b = ld256_evf(w2 + it * 256 + lane * 8);
            p += f8_dot_sh(a, h4, it * 64 + lane * 2);
            q += f8_dot_sh(b, h4, it * 64 + lane * 2);
        }
    }
#pragma unroll
    for (int o = 16; o; o >>= 1) {
        p += __shfl_xor_sync(0xffffffffu, p, o);
        q += __shfl_xor_sync(0xffffffffu, q, o);
    }
    o1 = p; o2 = q;
}

// cheap grid barrier: release-reduction arrival + acquire polling (no MEMBAR.GL)
#define GRID_BARRIER() do {                                                  \
    __syncthreads();                                                         \
    if (tid == 0) {                                                          \
        asm volatile("red.release.gpu.global.add.u64 [%0], %1;"              \
                     :: "l"(&g_bar), "l"(1ULL) : "memory");                  \
        bar_target += (unsigned long long)gridDim.x;                         \
        unsigned long long v;                                                \
        do {                                                                 \
            asm volatile("ld.acquire.gpu.global.u64 %0, [%1];"               \
                         : "=l"(v) : "l"(&g_bar) : "memory");                \
        } while (v < bar_target);                                            \
    }                                                                        \
    __syncthreads();                                                         \
} while (0)

__global__ void __launch_bounds__(NTHR, 1)
decoder_kernel(const int* __restrict__ y,
               const float* __restrict__ cv,
               const int* __restrict__ stride_p,
               const float* __restrict__ W_up,  const float* __restrict__ b_up,
               const float* __restrict__ W_ih0, const float* __restrict__ W_hh0,
               const float* __restrict__ b_ih0, const float* __restrict__ b_hh0,
               const float* __restrict__ W_ih1, const float* __restrict__ W_hh1,
               const float* __restrict__ b_ih1, const float* __restrict__ b_hh1,
               const float* __restrict__ W_out, const float* __restrict__ b_out,
               float* __restrict__ out)
{
    __shared__ __align__(16) float sh_h0[Hd];
    __shared__ __align__(16) float sh_h1[Hd];
    __shared__ __align__(16) float sh_c0[Hd];
    __shared__ __align__(16) float sh_c1[Hd];
    __shared__ float sh_pred[NWARP][8];   // per-warp deferred relu preds
    __shared__ float sh_red[NWARP];
    __shared__ unsigned long long sh_key[NWARP];
    __shared__ float sh_lse;

    const int tid  = threadIdx.x;
    const int bid  = blockIdx.x;
    const int wid  = tid >> 5;
    const int lane = tid & 31;
    const int gw   = bid * NWARP + wid;
    unsigned long long bar_target = 0ULL;

    const int nsteps = *stride_p;
    const int jrow = wid * NBLK + bid;     // gate row owned by this warp
    const bool dotsFirst = (gw & 1);       // stagger recurrent dots
    // balanced leftover row: rows [6*TOTW, 32000) spread over all blocks
    const bool hasLeft = (jrow < LEFT);
    const int lrow = 6 * TOTW + jrow;      // this warp's leftover vocab row

    // ---------------- init: ctx = cv0*cv1 ; h_init = W_up @ ctx + b_up -----
    sh_h0[tid] = cv[tid] * cv[Hd + tid];
    __syncthreads();
    if (jrow < Hd) {
        float d = warp_dot(W_up + (size_t)jrow * Hd, sh_h0, lane);
        if (lane == 0) g_hinit[jrow] = d + b_up[jrow];
    }
    GRID_BARRIER();
    {
        float hv = __ldcv(&g_hinit[tid]);
        sh_h0[tid] = hv; sh_c0[tid] = hv; sh_h1[tid] = hv; sh_c1[tid] = hv;
    }
    __syncthreads();

    // initial recurrent dots for step 0 (hh0 -> g_gate0, hh1 partial -> reg)
    float q1 = 0.f;
    if (jrow < G4) {
        float p, q;
        warp_dot_pair2_evl(W_hh0 + (size_t)jrow * Hd, sh_h0,
                           W_hh1 + (size_t)jrow * Hd, sh_h1, lane, p, q);
        q1 = q;
        if (lane == 0)
            g_gate0[jrow] = p + b_ih0[jrow] + b_hh0[jrow];
    }
    GRID_BARRIER();

    for (int t = 0; t < nsteps; ++t) {
        // ---- A2: token, lse reduce (warp0), layer-0 cell (block-redundant) ----
        float tok;
        if (t == 0) {
            tok = (float)__ldg(&y[0]);
        } else {
            unsigned long long key = __ldcv(&g_argmax[t - 1]);
            tok = (float)(0xFFFFFFFFu - (unsigned)(key & 0xFFFFFFFFull));
        }
        if (t > 0 && wid == 0) {
            float s = 0.f;
            for (int k = lane; k < NBLK; k += 32)
                s += __ldcv(&g_partial[t - 1][k]);
            s = warp_reduce_add(s);
            if (lane == 0) sh_lse = __logf(s);
        }
        {
            float pi = __ldcv(&g_gate0[tid])          + tok * __ldg(&W_ih0[tid]);
            float pf = __ldcv(&g_gate0[Hd + tid])     + tok * __ldg(&W_ih0[Hd + tid]);
            float pg = __ldcv(&g_gate0[2 * Hd + tid]) + tok * __ldg(&W_ih0[2 * Hd + tid]);
            float po = __ldcv(&g_gate0[3 * Hd + tid]) + tok * __ldg(&W_ih0[3 * Hd + tid]);
            float ig = sigmoidf_(pi);
            float fg = sigmoidf_(pf);
            float gg = tanhf(pg);
            float og = sigmoidf_(po);
            float c  = fg * sh_c0[tid] + ig * gg;
            sh_c0[tid] = c;
            sh_h0[tid] = og * tanhf(c);
        }
        __syncthreads();

        // ---- deferred write of step t-1 log-softmax ----
        if (t > 0) {
            if (wid < 6) {
                int r = bid * NWARP + lane + wid * TOTW;
                float v = sh_pred[lane][wid] - sh_lse;
                __stcs(&out[(size_t)(t - 1) * Vocab + r], v);
            }
            // leftover row (balanced): one scalar store per owning warp
            if (hasLeft && lane == 0) {
                float v = sh_pred[wid][6] - sh_lse;
                __stcs(&out[(size_t)(t - 1) * Vocab + lrow], v);
            }
        }

        // ---- phase B: only W_ih1·h0 on the critical path (L2-resident) ----
        if (jrow < G4) {
            float d = warp_dot_evl(W_ih1 + (size_t)jrow * Hd, sh_h0, lane);
            if (lane == 0)
                g_gate1[jrow] = q1 + d + b_ih1[jrow] + b_hh1[jrow];
        }
        GRID_BARRIER();

        // ---- B2: layer-1 cell (block-redundant) ----
        {
            float pi = __ldcv(&g_gate1[tid]);
            float pf = __ldcv(&g_gate1[Hd + tid]);
            float pg = __ldcv(&g_gate1[2 * Hd + tid]);
            float po = __ldcv(&g_gate1[3 * Hd + tid]);
            float ig = sigmoidf_(pi);
            float fg = sigmoidf_(pf);
            float gg = tanhf(pg);
            float og = sigmoidf_(po);
            float c  = fg * sh_c1[tid] + ig * gg;
            sh_c1[tid] = c;
            sh_h1[tid] = og * tanhf(c);
        }
        __syncthreads();

        // ---- phase C: vocab head + recurrent dots (staggered for mixing) ----
        if (dotsFirst && jrow < G4) {
            float p, q;
            warp_dot_pair2_evl(W_hh0 + (size_t)jrow * Hd, sh_h0,
                               W_hh1 + (size_t)jrow * Hd, sh_h1, lane, p, q);
            q1 = q;
            if (lane == 0)
                g_gate0[jrow] = p + b_ih0[jrow] + b_hh0[jrow];
        }

        float sumExp = 0.f;
        unsigned long long bestKey = 0ULL;
#pragma unroll
        for (int pr = 0; pr < 3; ++pr) {
            int r = gw + 2 * pr * TOTW;
            // per-warp-parity choice of which pair stays L2-resident (R7 map)
            bool cached = dotsFirst ? (pr == 2) : (pr == 0);
            float d0, d1;
            warp_dot_pair_pol(W_out + (size_t)r * Hd,
                              W_out + (size_t)(r + TOTW) * Hd, sh_h1, lane,
                              cached, d0, d1);
            if (lane == 0) {
                float p0 = fmaxf(d0 + b_out[r], 0.f);
                float p1 = fmaxf(d1 + b_out[r + TOTW], 0.f);
                sh_pred[wid][2 * pr]     = p0;
                sh_pred[wid][2 * pr + 1] = p1;
                sumExp += __expf(p0) + __expf(p1);
                unsigned long long k0 =
                    ((unsigned long long)__float_as_uint(p0) << 32)
                    | (unsigned long long)(0xFFFFFFFFu - (unsigned)r);
                unsigned long long k1 =
                    ((unsigned long long)__float_as_uint(p1) << 32)
                    | (unsigned long long)(0xFFFFFFFFu - (unsigned)(r + TOTW));
                if (k0 > bestKey) bestKey = k0;
                if (k1 > bestKey) bestKey = k1;
            }
        }
        if (hasLeft) {
            float d = warp_dot_evf(W_out + (size_t)lrow * Hd, sh_h1, lane);
            if (lane == 0) {
                float p = fmaxf(d + b_out[lrow], 0.f);
                sh_pred[wid][6] = p;
                sumExp += __expf(p);
                unsigned long long kk =
                    ((unsigned long long)__float_as_uint(p) << 32)
                    | (unsigned long long)(0xFFFFFFFFu - (unsigned)lrow);
                if (kk > bestKey) bestKey = kk;
            }
        }

        if (!dotsFirst && jrow < G4) {
            float p, q;
            warp_dot_pair2_evl(W_hh0 + (size_t)jrow * Hd, sh_h0,
                               W_hh1 + (size_t)jrow * Hd, sh_h1, lane, p, q);
            q1 = q;
            if (lane == 0)
                g_gate0[jrow] = p + b_ih0[jrow] + b_hh0[jrow];
        }

        if (lane == 0) { sh_red[wid] = sumExp; sh_key[wid] = bestKey; }
        __syncthreads();
        if (wid == 0) {
            float s = sh_red[lane];
            unsigned long long kk = sh_key[lane];
#pragma unroll
            for (int o = 16; o; o >>= 1) {
                s += __shfl_xor_sync(0xffffffffu, s, o);
                unsigned long long k2 = __shfl_xor_sync(0xffffffffu, kk, o);
                if (k2 > kk) kk = k2;
            }
            if (lane == 0) {
                g_partial[t][bid] = s;
                atomicMax(&g_argmax[t], kk);
            }
        }
        GRID_BARRIER();
    }

    // ---- final: lse + deferred write for the last step ----
    if (wid == 0) {
        float s = 0.f;
        for (int kk = lane; kk < NBLK; kk += 32)
            s += __ldcv(&g_partial[nsteps - 1][kk]);
        s = warp_reduce_add(s);
        if (lane == 0) sh_lse = __logf(s);
    }
    __syncthreads();
    if (wid < 6) {
        int r = bid * NWARP + lane + wid * TOTW;
        float v = sh_pred[lane][wid] - sh_lse;
        __stcs(&out[(size_t)(nsteps - 1) * Vocab + r], v);
    }
    if (hasLeft && lane == 0) {
        float v = sh_pred[wid][6] - sh_lse;
        __stcs(&out[(size_t)(nsteps - 1) * Vocab + lrow], v);
    }
}

extern "C" void kernel_launch(void* const* d_in, const int* in_sizes, int n_in,
                              void* d_out, int out_size)
{
    (void)in_sizes; (void)n_in; (void)out_size;
    dec_init<<<1, 256>>>();
    decoder_kernel<<<NBLK, NTHR>>>(
        (const int*)  d_in[0],   // y
        (const float*)d_in[1],   // context_vector
        (const int*)  d_in[2],   // stride
        (const float*)d_in[3],  (const float*)d_in[4],    // W_up, b_up
        (const float*)d_in[5],  (const float*)d_in[6],    // W_ih0, W_hh0
        (const float*)d_in[7],  (const float*)d_in[8],    // b_ih0, b_hh0
        (const float*)d_in[9],  (const float*)d_in[10],   // W_ih1, W_hh1
        (const float*)d_in[11], (const float*)d_in[12],   // b_ih1, b_hh1
        (const float*)d_in[13], (const float*)d_in[14],   // W_out, b_out
        (float*)d_out);
}

// round 17
// speedup vs baseline: 1.1694x; 1.1694x over previous
#include <cuda_runtime.h>
#include <math.h>

#define Hd     1024
#define G4     4096
#define Vocab  32000
#define NBLK   148
#define NTHR   1024
#define NWARP  32
#define TOTW   (NBLK * NWARP)   // 4736
#define MAXSTEPS 192

// ---------------- persistent device scratch (no allocations allowed) --------
__device__ float g_gate0[G4];     // layer-0 gate pre-act (W_hh0·h0 + biases)
__device__ float g_gate1[G4];     // layer-1 gate pre-act (full)
__device__ float g_hinit[Hd];
__device__ unsigned long long g_argmax[MAXSTEPS];
__device__ float g_partial[MAXSTEPS][NBLK];
__device__ unsigned long long g_bar;

__global__ void dec_init()
{
    if (threadIdx.x == 0) g_bar = 0ULL;
    for (int t = threadIdx.x; t < MAXSTEPS; t += blockDim.x) g_argmax[t] = 0ULL;
}

__device__ __forceinline__ float sigmoidf_(float x)
{
    return 1.f / (1.f + expf(-x));
}

__device__ __forceinline__ float warp_reduce_add(float v)
{
#pragma unroll
    for (int o = 16; o; o >>= 1) v += __shfl_xor_sync(0xffffffffu, v, o);
    return v;
}

// ---- 256-bit L2 eviction-policy loads (sm_103a: evict_* needs v8.b32) ------
struct F8 { float v[8]; };

__device__ __forceinline__ F8 ld256_evl(const float* p)   // keep in L2
{
    unsigned r0, r1, r2, r3, r4, r5, r6, r7;
    asm("ld.global.nc.L2::evict_last.v8.b32 {%0,%1,%2,%3,%4,%5,%6,%7}, [%8];"
        : "=r"(r0), "=r"(r1), "=r"(r2), "=r"(r3),
          "=r"(r4), "=r"(r5), "=r"(r6), "=r"(r7)
        : "l"(p));
    F8 f;
    f.v[0] = __uint_as_float(r0); f.v[1] = __uint_as_float(r1);
    f.v[2] = __uint_as_float(r2); f.v[3] = __uint_as_float(r3);
    f.v[4] = __uint_as_float(r4); f.v[5] = __uint_as_float(r5);
    f.v[6] = __uint_as_float(r6); f.v[7] = __uint_as_float(r7);
    return f;
}

__device__ __forceinline__ F8 ld256_evf(const float* p)   // stream through L2
{
    unsigned r0, r1, r2, r3, r4, r5, r6, r7;
    asm("ld.global.nc.L2::evict_first.v8.b32 {%0,%1,%2,%3,%4,%5,%6,%7}, [%8];"
        : "=r"(r0), "=r"(r1), "=r"(r2), "=r"(r3),
          "=r"(r4), "=r"(r5), "=r"(r6), "=r"(r7)
        : "l"(p));
    F8 f;
    f.v[0] = __uint_as_float(r0); f.v[1] = __uint_as_float(r1);
    f.v[2] = __uint_as_float(r2); f.v[3] = __uint_as_float(r3);
    f.v[4] = __uint_as_float(r4); f.v[5] = __uint_as_float(r5);
    f.v[6] = __uint_as_float(r6); f.v[7] = __uint_as_float(r7);
    return f;
}

__device__ __forceinline__ float f8_dot_sh(const F8& a, const float4* h4,
                                           int base)
{
    float4 u0 = h4[base];
    float4 u1 = h4[base + 1];
    return a.v[0] * u0.x + a.v[1] * u0.y + a.v[2] * u0.z + a.v[3] * u0.w
         + a.v[4] * u1.x + a.v[5] * u1.y + a.v[6] * u1.z + a.v[7] * u1.w;
}

// plain warp dot (init only)
__device__ __forceinline__ float warp_dot(const float* __restrict__ w,
                                          const float* __restrict__ sh,
                                          int lane)
{
    const float4* w4 = reinterpret_cast<const float4*>(w);
    const float4* h4 = reinterpret_cast<const float4*>(sh);
    float a0 = 0.f;
#pragma unroll
    for (int it = 0; it < 8; ++it) {
        float4 x = w4[it * 32 + lane];
        float4 u = h4[it * 32 + lane];
        a0 += x.x * u.x + x.y * u.y + x.z * u.z + x.w * u.w;
    }
    return warp_reduce_add(a0);
}

// L2-resident (evict_last) warp dot — LSTM weights
__device__ __forceinline__ float warp_dot_evl(const float* __restrict__ w,
                                              const float* __restrict__ sh,
                                              int lane)
{
    const float4* h4 = reinterpret_cast<const float4*>(sh);
    float a0 = 0.f;
#pragma unroll
    for (int it = 0; it < 4; ++it) {
        F8 x = ld256_evl(w + it * 256 + lane * 8);
        a0 += f8_dot_sh(x, h4, it * 64 + lane * 2);
    }
    return warp_reduce_add(a0);
}

// streaming single-row dot (W_out leftover row)
__device__ __forceinline__ float warp_dot_evf(const float* __restrict__ w,
                                              const float* __restrict__ sh,
                                              int lane)
{
    const float4* h4 = reinterpret_cast<const float4*>(sh);
    float a0 = 0.f;
#pragma unroll
    for (int it = 0; it < 4; ++it) {
        F8 x = ld256_evf(w + it * 256 + lane * 8);
        a0 += f8_dot_sh(x, h4, it * 64 + lane * 2);
    }
    return warp_reduce_add(a0);
}

// two rows against two different vectors, evict_last (recurrent dots)
__device__ __forceinline__ void warp_dot_pair2_evl(const float* __restrict__ w1,
                                                   const float* __restrict__ s1,
                                                   const float* __restrict__ w2,
                                                   const float* __restrict__ s2,
                                                   int lane, float& o1, float& o2)
{
    const float4* h4 = reinterpret_cast<const float4*>(s1);
    const float4* g4 = reinterpret_cast<const float4*>(s2);
    float p = 0.f, q = 0.f;
#pragma unroll
    for (int it = 0; it < 4; ++it) {
        F8 a = ld256_evl(w1 + it * 256 + lane * 8);
        F8 b = ld256_evl(w2 + it * 256 + lane * 8);
        p += f8_dot_sh(a, h4, it * 64 + lane * 2);
        q += f8_dot_sh(b, g4, it * 64 + lane * 2);
    }
#pragma unroll
    for (int o = 16; o; o >>= 1) {
        p += __shfl_xor_sync(0xffffffffu, p, o);
        q += __shfl_xor_sync(0xffffffffu, q, o);
    }
    o1 = p; o2 = q;
}

// two independent W_out rows vs same vector; policy chosen per call (warp-uniform)
__device__ __forceinline__ void warp_dot_pair_pol(const float* __restrict__ w1,
                                                  const float* __restrict__ w2,
                                                  const float* __restrict__ sh,
                                                  int lane, bool cached,
                                                  float& o1, float& o2)
{
    const float4* h4 = reinterpret_cast<const float4*>(sh);
    float p = 0.f, q = 0.f;
    if (cached) {
#pragma unroll
        for (int it = 0; it < 4; ++it) {
            F8 a = ld256_evl(w1 + it * 256 + lane * 8);
            F8 b = ld256_evl(w2 + it * 256 + lane * 8);
            p += f8_dot_sh(a, h4, it * 64 + lane * 2);
            q += f8_dot_sh(b, h4, it * 64 + lane * 2);
        }
    } else {
#pragma unroll
        for (int it = 0; it < 4; ++it) {
            F8 a = ld256_evf(w1 + it * 256 + lane * 8);
            F8 b = ld256_evf(w2 + it * 256 + lane * 8);
            p += f8_dot_sh(a, h4, it * 64 + lane * 2);
            q += f8_dot_sh(b, h4, it * 64 + lane * 2);
        }
    }
#pragma unroll
    for (int o = 16; o; o >>= 1) {
        p += __shfl_xor_sync(0xffffffffu, p, o);
        q += __shfl_xor_sync(0xffffffffu, q, o);
    }
    o1 = p; o2 = q;
}

#define GRID_BARRIER() do {                                                  \
    __syncthreads();                                                         \
    if (tid == 0) {                                                          \
        __threadfence();                                                     \
        atomicAdd(&g_bar, 1ULL);                                             \
        bar_target += (unsigned long long)gridDim.x;                         \
        while (*((volatile unsigned long long*)&g_bar) < bar_target) { }     \
    }                                                                        \
    __syncthreads();                                                         \
} while (0)

__global__ void __launch_bounds__(NTHR, 1)
decoder_kernel(const int* __restrict__ y,
               const float* __restrict__ cv,
               const int* __restrict__ stride_p,
               const float* __restrict__ W_up,  const float* __restrict__ b_up,
               const float* __restrict__ W_ih0, const float* __restrict__ W_hh0,
               const float* __restrict__ b_ih0, const float* __restrict__ b_hh0,
               const float* __restrict__ W_ih1, const float* __restrict__ W_hh1,
               const float* __restrict__ b_ih1, const float* __restrict__ b_hh1,
               const float* __restrict__ W_out, const float* __restrict__ b_out,
               float* __restrict__ out)
{
    __shared__ __align__(16) float sh_h0[Hd];
    __shared__ __align__(16) float sh_h1[Hd];
    __shared__ __align__(16) float sh_c0[Hd];
    __shared__ __align__(16) float sh_c1[Hd];
    __shared__ float sh_pred[NWARP][8];   // per-warp deferred relu preds
    __shared__ float sh_red[NWARP];
    __shared__ unsigned long long sh_key[NWARP];
    __shared__ float sh_lse;

    const int tid  = threadIdx.x;
    const int bid  = blockIdx.x;
    const int wid  = tid >> 5;
    const int lane = tid & 31;
    const int gw   = bid * NWARP + wid;
    unsigned long long bar_target = 0ULL;

    const int nsteps = *stride_p;
    const int jrow = wid * NBLK + bid;     // gate row owned by this warp
    const bool dotsFirst = (gw & 1);       // stagger recurrent dots

    // ---------------- init: ctx = cv0*cv1 ; h_init = W_up @ ctx + b_up -----
    sh_h0[tid] = cv[tid] * cv[Hd + tid];
    __syncthreads();
    if (jrow < Hd) {
        float d = warp_dot(W_up + (size_t)jrow * Hd, sh_h0, lane);
        if (lane == 0) g_hinit[jrow] = d + b_up[jrow];
    }
    GRID_BARRIER();
    {
        float hv = __ldcv(&g_hinit[tid]);
        sh_h0[tid] = hv; sh_c0[tid] = hv; sh_h1[tid] = hv; sh_c1[tid] = hv;
    }
    __syncthreads();

    // initial recurrent dots for step 0 (hh0 -> g_gate0, hh1 partial -> reg)
    float q1 = 0.f;
    if (jrow < G4) {
        float p, q;
        warp_dot_pair2_evl(W_hh0 + (size_t)jrow * Hd, sh_h0,
                           W_hh1 + (size_t)jrow * Hd, sh_h1, lane, p, q);
        q1 = q;
        if (lane == 0)
            g_gate0[jrow] = p + b_ih0[jrow] + b_hh0[jrow];
    }
    GRID_BARRIER();

    for (int t = 0; t < nsteps; ++t) {
        // ---- A2: token, lse reduce (warp0), layer-0 cell (block-redundant) ----
        float tok;
        if (t == 0) {
            tok = (float)__ldg(&y[0]);
        } else {
            unsigned long long key = __ldcv(&g_argmax[t - 1]);
            tok = (float)(0xFFFFFFFFu - (unsigned)(key & 0xFFFFFFFFull));
        }
        if (t > 0 && wid == 0) {
            float s = 0.f;
            for (int k = lane; k < NBLK; k += 32)
                s += __ldcv(&g_partial[t - 1][k]);
            s = warp_reduce_add(s);
            if (lane == 0) sh_lse = logf(s);
        }
        {
            float pi = __ldcv(&g_gate0[tid])          + tok * __ldg(&W_ih0[tid]);
            float pf = __ldcv(&g_gate0[Hd + tid])     + tok * __ldg(&W_ih0[Hd + tid]);
            float pg = __ldcv(&g_gate0[2 * Hd + tid]) + tok * __ldg(&W_ih0[2 * Hd + tid]);
            float po = __ldcv(&g_gate0[3 * Hd + tid]) + tok * __ldg(&W_ih0[3 * Hd + tid]);
            float ig = sigmoidf_(pi);
            float fg = sigmoidf_(pf);
            float gg = tanhf(pg);
            float og = sigmoidf_(po);
            float c  = fg * sh_c0[tid] + ig * gg;
            sh_c0[tid] = c;
            sh_h0[tid] = og * tanhf(c);
        }
        __syncthreads();

        // ---- deferred coalesced write of step t-1 log-softmax ----
        if (t > 0 && wid < 7) {
            int r = bid * NWARP + lane + wid * TOTW;
            if (r < Vocab) {
                float v = sh_pred[lane][wid] - sh_lse;
                __stcs(&out[(size_t)(t - 1) * Vocab + r], v);
            }
        }

        // ---- phase B: only W_ih1·h0 on the critical path (L2-resident) ----
        if (jrow < G4) {
            float d = warp_dot_evl(W_ih1 + (size_t)jrow * Hd, sh_h0, lane);
            if (lane == 0)
                g_gate1[jrow] = q1 + d + b_ih1[jrow] + b_hh1[jrow];
        }
        GRID_BARRIER();

        // ---- B2: layer-1 cell (block-redundant) ----
        {
            float pi = __ldcv(&g_gate1[tid]);
            float pf = __ldcv(&g_gate1[Hd + tid]);
            float pg = __ldcv(&g_gate1[2 * Hd + tid]);
            float po = __ldcv(&g_gate1[3 * Hd + tid]);
            float ig = sigmoidf_(pi);
            float fg = sigmoidf_(pf);
            float gg = tanhf(pg);
            float og = sigmoidf_(po);
            float c  = fg * sh_c1[tid] + ig * gg;
            sh_c1[tid] = c;
            sh_h1[tid] = og * tanhf(c);
        }
        __syncthreads();

        // ---- phase C: vocab head + recurrent dots (staggered for mixing) ----
        if (dotsFirst && jrow < G4) {
            float p, q;
            warp_dot_pair2_evl(W_hh0 + (size_t)jrow * Hd, sh_h0,
                               W_hh1 + (size_t)jrow * Hd, sh_h1, lane, p, q);
            q1 = q;
            if (lane == 0)
                g_gate0[jrow] = p + b_ih0[jrow] + b_hh0[jrow];
        }

        float sumExp = 0.f;
        unsigned long long bestKey = 0ULL;
        int r = gw;
        int k = 0;
        int pr = 0;
        while (r + TOTW < Vocab) {
            // per-warp-parity choice of which pair stays L2-resident
            bool cached = dotsFirst ? (pr == 2) : (pr == 0);
            float d0, d1;
            warp_dot_pair_pol(W_out + (size_t)r * Hd,
                              W_out + (size_t)(r + TOTW) * Hd, sh_h1, lane,
                              cached, d0, d1);
            if (lane == 0) {
                float p0 = fmaxf(d0 + b_out[r], 0.f);
                float p1 = fmaxf(d1 + b_out[r + TOTW], 0.f);
                sh_pred[wid][k]     = p0;
                sh_pred[wid][k + 1] = p1;
                sumExp += expf(p0) + expf(p1);
                unsigned long long k0 =
                    ((unsigned long long)__float_as_uint(p0) << 32)
                    | (unsigned long long)(0xFFFFFFFFu - (unsigned)r);
                unsigned long long k1 =
                    ((unsigned long long)__float_as_uint(p1) << 32)
                    | (unsigned long long)(0xFFFFFFFFu - (unsigned)(r + TOTW));
                if (k0 > bestKey) bestKey = k0;
                if (k1 > bestKey) bestKey = k1;
            }
            r += 2 * TOTW;
            k += 2;
            pr++;
        }
        if (r < Vocab) {
            float d = warp_dot_evf(W_out + (size_t)r * Hd, sh_h1, lane);
            if (lane == 0) {
                float p = fmaxf(d + b_out[r], 0.f);
                sh_pred[wid][k] = p;
                sumExp += expf(p);
                unsigned long long kk =
                    ((unsigned long long)__float_as_uint(p) << 32)
                    | (unsigned long long)(0xFFFFFFFFu - (unsigned)r);
                if (kk > bestKey) bestKey = kk;
            }
        }

        if (!dotsFirst && jrow < G4) {
            float p, q;
            warp_dot_pair2_evl(W_hh0 + (size_t)jrow * Hd, sh_h0,
                               W_hh1 + (size_t)jrow * Hd, sh_h1, lane, p, q);
            q1 = q;
            if (lane == 0)
                g_gate0[jrow] = p + b_ih0[jrow] + b_hh0[jrow];
        }

        if (lane == 0) { sh_red[wid] = sumExp; sh_key[wid] = bestKey; }
        __syncthreads();
        if (wid == 0) {
            float s = sh_red[lane];
            unsigned long long kk = sh_key[lane];
#pragma unroll
            for (int o = 16; o; o >>= 1) {
                s += __shfl_xor_sync(0xffffffffu, s, o);
                unsigned long long k2 = __shfl_xor_sync(0xffffffffu, kk, o);
                if (k2 > kk) kk = k2;
            }
            if (lane == 0) {
                g_partial[t][bid] = s;
                atomicMax(&g_argmax[t], kk);
            }
        }
        GRID_BARRIER();
    }

    // ---- final: lse + deferred write for the last step ----
    if (wid == 0) {
        float s = 0.f;
        for (int kk = lane; kk < NBLK; kk += 32)
            s += __ldcv(&g_partial[nsteps - 1][kk]);
        s = warp_reduce_add(s);
        if (lane == 0) sh_lse = logf(s);
    }
    __syncthreads();
    if (wid < 7) {
        int r = bid * NWARP + lane + wid * TOTW;
        if (r < Vocab) {
            float v = sh_pred[lane][wid] - sh_lse;
            __stcs(&out[(size_t)(nsteps - 1) * Vocab + r], v);
        }
    }
}

extern "C" void kernel_launch(void* const* d_in, const int* in_sizes, int n_in,
                              void* d_out, int out_size)
{
    (void)in_sizes; (void)n_in; (void)out_size;
    dec_init<<<1, 256>>>();
    decoder_kernel<<<NBLK, NTHR>>>(
        (const int*)  d_in[0],   // y
        (const float*)d_in[1],   // context_vector
        (const int*)  d_in[2],   // stride
        (const float*)d_in[3],  (const float*)d_in[4],    // W_up, b_up
        (const float*)d_in[5],  (const float*)d_in[6],    // W_ih0, W_hh0
        (const float*)d_in[7],  (const float*)d_in[8],    // b_ih0, b_hh0
        (const float*)d_in[9],  (const float*)d_in[10],   // W_ih1, W_hh1
        (const float*)d_in[11], (const float*)d_in[12],   // b_ih1, b_hh1
        (const float*)d_in[13], (const float*)d_in[14],   // W_out, b_out
        (float*)d_out);
}